// round 1
// baseline (speedup 1.0000x reference)
#include <cuda_runtime.h>
#include <math.h>

#define N_JOINTS 50
#define ROW 150
#define ROWS_PER_BLK 8
#define THREADS 256
#define TOTAL_ROWS (128 * 1024)
#define N_BLOCKS (TOTAL_ROWS / ROWS_PER_BLK)
#define TINY 1.17549435082228750797e-38f

// Cross-block accumulators: [0] = sum |p - t|, [1] = sum (m*(p_dir - t_dir))^2
__device__ double g_acc[2];

__global__ void zero_acc_kernel() {
    g_acc[0] = 0.0;
    g_acc[1] = 0.0;
}

__global__ __launch_bounds__(THREADS) void bone_loss_kernel(
    const float* __restrict__ preds,
    const float* __restrict__ targets)
{
    __shared__ float sp[ROWS_PER_BLK][ROW];
    __shared__ float st[ROWS_PER_BLK][ROW];
    __shared__ float s_abs[ROWS_PER_BLK];
    __shared__ float s_sq[ROWS_PER_BLK];

    const int wid = threadIdx.x >> 5;
    const int lid = threadIdx.x & 31;

    const long long row = (long long)blockIdx.x * ROWS_PER_BLK + wid;
    const float* __restrict__ pr = preds   + row * ROW;
    const float* __restrict__ tr = targets + row * ROW;

    // ---- Phase 1: load + mask + staged into SMEM, accumulate L1 term ----
    float abs_sum = 0.0f;
    #pragma unroll
    for (int j = lid; j < ROW; j += 32) {
        float tv = __ldg(tr + j);
        float pv = __ldg(pr + j);
        // mask = (tv != 0); masked values
        float ps, ts;
        if (tv != 0.0f) { ps = pv; ts = tv; }
        else            { ps = 0.0f; ts = 0.0f; }
        sp[wid][j] = ps;
        st[wid][j] = ts;
        abs_sum += fabsf(ps - ts);
    }
    __syncwarp();

    // ---- Phase 2: per-bone direction terms ----
    // Bone i connects joint i and joint (i+1) % 50.
    // mask at output position 3i+c equals (st[3i+c] != 0): st holds tv where
    // mask==1 (tv != 0 there) and 0 where mask==0.
    float sq_sum = 0.0f;
    for (int bi = lid; bi < N_JOINTS; bi += 32) {
        const int a = 3 * bi;
        const int b = 3 * ((bi + 1 == N_JOINTS) ? 0 : (bi + 1));

        float pa0 = sp[wid][a],     pa1 = sp[wid][a + 1], pa2 = sp[wid][a + 2];
        float pb0 = sp[wid][b],     pb1 = sp[wid][b + 1], pb2 = sp[wid][b + 2];
        float ta0 = st[wid][a],     ta1 = st[wid][a + 1], ta2 = st[wid][a + 2];
        float tb0 = st[wid][b],     tb1 = st[wid][b + 1], tb2 = st[wid][b + 2];

        float pd0 = pa0 - pb0, pd1 = pa1 - pb1, pd2 = pa2 - pb2;
        float td0 = ta0 - tb0, td1 = ta1 - tb1, td2 = ta2 - tb2;

        float plen = sqrtf(fmaf(pd0, pd0, fmaf(pd1, pd1, pd2 * pd2)));
        float tlen = sqrtf(fmaf(td0, td0, fmaf(td1, td1, td2 * td2)));

        float pinv = 1.0f / (plen + TINY);
        float tinv = 1.0f / (tlen + TINY);

        // m*(p_dir - t_dir), m in {0,1}
        float d0 = (ta0 != 0.0f) ? (pd0 * pinv - td0 * tinv) : 0.0f;
        float d1 = (ta1 != 0.0f) ? (pd1 * pinv - td1 * tinv) : 0.0f;
        float d2 = (ta2 != 0.0f) ? (pd2 * pinv - td2 * tinv) : 0.0f;

        sq_sum = fmaf(d0, d0, sq_sum);
        sq_sum = fmaf(d1, d1, sq_sum);
        sq_sum = fmaf(d2, d2, sq_sum);
    }

    // ---- warp reduction ----
    #pragma unroll
    for (int off = 16; off > 0; off >>= 1) {
        abs_sum += __shfl_down_sync(0xFFFFFFFFu, abs_sum, off);
        sq_sum  += __shfl_down_sync(0xFFFFFFFFu, sq_sum,  off);
    }
    if (lid == 0) {
        s_abs[wid] = abs_sum;
        s_sq[wid]  = sq_sum;
    }
    __syncthreads();

    // ---- block reduction + global double atomics ----
    if (threadIdx.x == 0) {
        float ba = 0.0f, bs = 0.0f;
        #pragma unroll
        for (int w = 0; w < ROWS_PER_BLK; w++) { ba += s_abs[w]; bs += s_sq[w]; }
        atomicAdd(&g_acc[0], (double)ba);
        atomicAdd(&g_acc[1], (double)bs);
    }
}

__global__ void finalize_kernel(float* __restrict__ out) {
    const double N = (double)TOTAL_ROWS * (double)ROW; // 19,660,800
    double loss = (g_acc[0] / N + 0.1 * (g_acc[1] / N)) * 0.1;
    out[0] = (float)loss;
}

extern "C" void kernel_launch(void* const* d_in, const int* in_sizes, int n_in,
                              void* d_out, int out_size) {
    const float* preds   = (const float*)d_in[0];
    const float* targets = (const float*)d_in[1];
    float* out = (float*)d_out;

    zero_acc_kernel<<<1, 1>>>();
    bone_loss_kernel<<<N_BLOCKS, THREADS>>>(preds, targets);
    finalize_kernel<<<1, 1>>>(out);
}

// round 2
// speedup vs baseline: 1.2574x; 1.2574x over previous
#include <cuda_runtime.h>
#include <math.h>

#define N_JOINTS 50
#define ROW 150
#define ROWS_PER_BLK 32
#define THREADS 256
#define TOTAL_ROWS (128 * 1024)
#define N_BLOCKS (TOTAL_ROWS / ROWS_PER_BLK)      // 4096
#define ELEMS (ROWS_PER_BLK * ROW)                // 4800 floats per tensor per block
#define VECS (ELEMS / 4)                          // 1200 float4
#define TINY 1.17549435082228750797e-38f

// Per-block partials, fully overwritten every launch (no zeroing needed).
__device__ float g_part_abs[N_BLOCKS];
__device__ float g_part_sq[N_BLOCKS];

__global__ __launch_bounds__(THREADS) void bone_loss_kernel(
    const float* __restrict__ preds,
    const float* __restrict__ targets)
{
    __shared__ float sp[ELEMS];
    __shared__ float st[ELEMS];
    __shared__ float s_abs[THREADS / 32];
    __shared__ float s_sq[THREADS / 32];

    const int tid = threadIdx.x;
    const int wid = tid >> 5;
    const int lid = tid & 31;

    // ---- Phase 1: vectorized load + mask + stage to SMEM + L1 term ----
    const long long vbase = (long long)blockIdx.x * VECS;
    const float4* __restrict__ p4 = (const float4*)preds + vbase;
    const float4* __restrict__ t4 = (const float4*)targets + vbase;
    float4* sp4 = (float4*)sp;
    float4* st4 = (float4*)st;

    float abs_sum = 0.0f;
    #pragma unroll
    for (int i = tid; i < VECS; i += THREADS) {
        float4 t = __ldg(t4 + i);
        float4 p = __ldg(p4 + i);
        // mask = (t != 0); masked p and t
        float4 pm, tm;
        pm.x = (t.x != 0.0f) ? p.x : 0.0f;  tm.x = t.x;  // t already 0 where masked
        pm.y = (t.y != 0.0f) ? p.y : 0.0f;  tm.y = t.y;
        pm.z = (t.z != 0.0f) ? p.z : 0.0f;  tm.z = t.z;
        pm.w = (t.w != 0.0f) ? p.w : 0.0f;  tm.w = t.w;
        sp4[i] = pm;
        st4[i] = tm;
        abs_sum += fabsf(pm.x - tm.x) + fabsf(pm.y - tm.y)
                 + fabsf(pm.z - tm.z) + fabsf(pm.w - tm.w);
    }
    __syncthreads();

    // ---- Phase 2: per-bone direction terms ----
    // Warp wid handles 4 rows; 50 bones per row strided over 32 lanes.
    float sq_sum = 0.0f;
    #pragma unroll
    for (int r = 0; r < 4; r++) {
        const int roff = (wid * 4 + r) * ROW;
        for (int bi = lid; bi < N_JOINTS; bi += 32) {
            const int a = roff + 3 * bi;
            const int b = roff + 3 * ((bi + 1 == N_JOINTS) ? 0 : (bi + 1));

            float pd0 = sp[a]     - sp[b];
            float pd1 = sp[a + 1] - sp[b + 1];
            float pd2 = sp[a + 2] - sp[b + 2];
            float ta0 = st[a], ta1 = st[a + 1], ta2 = st[a + 2];
            float td0 = ta0 - st[b];
            float td1 = ta1 - st[b + 1];
            float td2 = ta2 - st[b + 2];

            float plen = sqrtf(fmaf(pd0, pd0, fmaf(pd1, pd1, pd2 * pd2)));
            float tlen = sqrtf(fmaf(td0, td0, fmaf(td1, td1, td2 * td2)));
            float pinv = 1.0f / (plen + TINY);
            float tinv = 1.0f / (tlen + TINY);

            float d0 = (ta0 != 0.0f) ? (pd0 * pinv - td0 * tinv) : 0.0f;
            float d1 = (ta1 != 0.0f) ? (pd1 * pinv - td1 * tinv) : 0.0f;
            float d2 = (ta2 != 0.0f) ? (pd2 * pinv - td2 * tinv) : 0.0f;

            sq_sum = fmaf(d0, d0, sq_sum);
            sq_sum = fmaf(d1, d1, sq_sum);
            sq_sum = fmaf(d2, d2, sq_sum);
        }
    }

    // ---- warp + block reduction ----
    #pragma unroll
    for (int off = 16; off > 0; off >>= 1) {
        abs_sum += __shfl_down_sync(0xFFFFFFFFu, abs_sum, off);
        sq_sum  += __shfl_down_sync(0xFFFFFFFFu, sq_sum,  off);
    }
    if (lid == 0) { s_abs[wid] = abs_sum; s_sq[wid] = sq_sum; }
    __syncthreads();

    if (tid == 0) {
        float ba = 0.0f, bs = 0.0f;
        #pragma unroll
        for (int w = 0; w < THREADS / 32; w++) { ba += s_abs[w]; bs += s_sq[w]; }
        g_part_abs[blockIdx.x] = ba;
        g_part_sq[blockIdx.x]  = bs;
    }
}

__global__ __launch_bounds__(256) void finalize_kernel(float* __restrict__ out) {
    __shared__ double sh_a[8], sh_s[8];
    const int tid = threadIdx.x;
    double a = 0.0, s = 0.0;
    for (int i = tid; i < N_BLOCKS; i += 256) {
        a += (double)g_part_abs[i];
        s += (double)g_part_sq[i];
    }
    #pragma unroll
    for (int off = 16; off > 0; off >>= 1) {
        a += __shfl_down_sync(0xFFFFFFFFu, a, off);
        s += __shfl_down_sync(0xFFFFFFFFu, s, off);
    }
    if ((tid & 31) == 0) { sh_a[tid >> 5] = a; sh_s[tid >> 5] = s; }
    __syncthreads();
    if (tid == 0) {
        double ta = 0.0, ts = 0.0;
        #pragma unroll
        for (int w = 0; w < 8; w++) { ta += sh_a[w]; ts += sh_s[w]; }
        const double N = (double)TOTAL_ROWS * (double)ROW;
        out[0] = (float)((ta / N + 0.1 * (ts / N)) * 0.1);
    }
}

extern "C" void kernel_launch(void* const* d_in, const int* in_sizes, int n_in,
                              void* d_out, int out_size) {
    const float* preds   = (const float*)d_in[0];
    const float* targets = (const float*)d_in[1];
    float* out = (float*)d_out;

    bone_loss_kernel<<<N_BLOCKS, THREADS>>>(preds, targets);
    finalize_kernel<<<1, 256>>>(out);
}